// round 3
// baseline (speedup 1.0000x reference)
#include <cuda_runtime.h>
#include <cuda_bf16.h>

// Sampler_51419348468365
//
// out = stop_gradient(1 - y) + y  ==  1.0f value-wise (fp32 rounding
// <= ~1.2e-7, tolerance 1e-3). Kernel writes constant 1.0f to out_size floats.
//
// R2: single-wave grid. 128 CTAs (<=148 SMs, one wave, no wave transition),
// 256 threads, 8 independent float4 stores per thread (MLP=8, coalesced:
// consecutive threads hit consecutive float4s within each chunk). Exact fit
// for out_size = 2^20; generic path handles other sizes.

__global__ __launch_bounds__(256, 1)
void Sampler_fill_ones(float4* __restrict__ out4, int n4,
                       float* __restrict__ out_tail, int n_total) {
    const float4 ones = make_float4(1.0f, 1.0f, 1.0f, 1.0f);
    const int nthreads = gridDim.x * 256;          // 32768
    const int tid = blockIdx.x * 256 + threadIdx.x;

    // Fast path: n4 == nthreads * 8 (the actual shape). Fully unrolled,
    // 8 independent stores issued back-to-back.
    if (n4 == nthreads * 8) {
#pragma unroll
        for (int j = 0; j < 8; ++j) {
            out4[j * nthreads + tid] = ones;
        }
        return;
    }

    // Generic path (never taken for this problem's shape).
    for (int i = tid; i < n4; i += nthreads) out4[i] = ones;
    for (int i = 4 * n4 + tid; i < n_total; i += nthreads) out_tail[i] = 1.0f;
}

extern "C" void kernel_launch(void* const* d_in, const int* in_sizes, int n_in,
                              void* d_out, int out_size) {
    (void)d_in; (void)in_sizes; (void)n_in;
    float* out = (float*)d_out;
    int n4 = out_size / 4;   // 262144
    Sampler_fill_ones<<<128, 256>>>((float4*)out, n4, out, out_size);
}